// round 1
// baseline (speedup 1.0000x reference)
#include <cuda_runtime.h>
#include <cstdint>

#define DM     1024
#define NH     16
#define DH     64
#define SEQ    2048
#define BATCH  2
#define M_TOT  (BATCH * SEQ)   // 4096

// Scratch (no allocations allowed)
__device__ float g_Q[(size_t)M_TOT * DM];
__device__ float g_K[(size_t)M_TOT * DM];
__device__ float g_V[(size_t)M_TOT * DM];
__device__ float g_O[(size_t)M_TOT * DM];

// ---------------------------------------------------------------------------
// GEMM: Y[m,n] = sum_k X[m,k] * W[n,k]   (Y = X @ W^T), M=4096, N=K=1024
// 128x128 block tile, BK=16, 256 threads, 8x8 micro-tile.
// ---------------------------------------------------------------------------
__global__ __launch_bounds__(256) void gemm_xwt(const float* __restrict__ X,
                                                const float* __restrict__ W,
                                                float* __restrict__ Y) {
    __shared__ __align__(16) float As[16][132];
    __shared__ __align__(16) float Bs[16][132];

    const int t  = threadIdx.x;
    const int m0 = blockIdx.y * 128;
    const int n0 = blockIdx.x * 128;
    const int ty = t >> 4;          // 0..15
    const int tx = t & 15;          // 0..15

    float acc[8][8];
#pragma unroll
    for (int r = 0; r < 8; r++)
#pragma unroll
        for (int c = 0; c < 8; c++) acc[r][c] = 0.f;

    for (int k0 = 0; k0 < DM; k0 += 16) {
#pragma unroll
        for (int i = 0; i < 2; i++) {
            int f   = t + i * 256;
            int row = f >> 2;            // 0..127
            int q   = (f & 3) << 2;      // 0,4,8,12
            float4 a = *(const float4*)(X + (size_t)(m0 + row) * DM + k0 + q);
            As[q + 0][row] = a.x; As[q + 1][row] = a.y;
            As[q + 2][row] = a.z; As[q + 3][row] = a.w;
            float4 b = *(const float4*)(W + (size_t)(n0 + row) * DM + k0 + q);
            Bs[q + 0][row] = b.x; Bs[q + 1][row] = b.y;
            Bs[q + 2][row] = b.z; Bs[q + 3][row] = b.w;
        }
        __syncthreads();

#pragma unroll
        for (int kk = 0; kk < 16; kk++) {
            float4 a0 = *(const float4*)(&As[kk][ty * 8]);
            float4 a1 = *(const float4*)(&As[kk][ty * 8 + 4]);
            float4 b0 = *(const float4*)(&Bs[kk][tx * 8]);
            float4 b1 = *(const float4*)(&Bs[kk][tx * 8 + 4]);
            float ra[8] = {a0.x, a0.y, a0.z, a0.w, a1.x, a1.y, a1.z, a1.w};
            float rb[8] = {b0.x, b0.y, b0.z, b0.w, b1.x, b1.y, b1.z, b1.w};
#pragma unroll
            for (int r = 0; r < 8; r++)
#pragma unroll
                for (int c = 0; c < 8; c++)
                    acc[r][c] = fmaf(ra[r], rb[c], acc[r][c]);
        }
        __syncthreads();
    }

#pragma unroll
    for (int r = 0; r < 8; r++) {
        float* yrow = Y + (size_t)(m0 + ty * 8 + r) * DM + n0 + tx * 8;
        float4 v0 = {acc[r][0], acc[r][1], acc[r][2], acc[r][3]};
        float4 v1 = {acc[r][4], acc[r][5], acc[r][6], acc[r][7]};
        *(float4*)(yrow)     = v0;
        *(float4*)(yrow + 4) = v1;
    }
}

// ---------------------------------------------------------------------------
// Flash attention: per (b,h), Q[2048,64] x K[2048,64] -> softmax -> @ V
// Block handles 64 q-rows; loops over 32 k-tiles of 64 rows.
// Threads: 256 (16x16), 4x4 micro-tiles for both S and O GEMMs.
// Shared: Qts (d-major, Q^T * scale), Kts (d-major, reused as P^T), Vs.
// ---------------------------------------------------------------------------
#define FPAD 68
#define FLASH_SMEM (3 * 64 * FPAD * 4)

__device__ __forceinline__ float grp_max16(float v) {
    v = fmaxf(v, __shfl_xor_sync(0xffffffffu, v, 1));
    v = fmaxf(v, __shfl_xor_sync(0xffffffffu, v, 2));
    v = fmaxf(v, __shfl_xor_sync(0xffffffffu, v, 4));
    v = fmaxf(v, __shfl_xor_sync(0xffffffffu, v, 8));
    return v;
}
__device__ __forceinline__ float grp_sum16(float v) {
    v += __shfl_xor_sync(0xffffffffu, v, 1);
    v += __shfl_xor_sync(0xffffffffu, v, 2);
    v += __shfl_xor_sync(0xffffffffu, v, 4);
    v += __shfl_xor_sync(0xffffffffu, v, 8);
    return v;
}

__global__ __launch_bounds__(256) void flash_attn(const float* __restrict__ Q,
                                                  const float* __restrict__ K,
                                                  const float* __restrict__ V,
                                                  float* __restrict__ O) {
    extern __shared__ __align__(16) float sm[];
    float* Qts = sm;                 // [64][FPAD]  Qts[d][r]
    float* Kts = sm + 64 * FPAD;     // [64][FPAD]  Kts[d][c]; reused as Pts[k][r]
    float* Vs  = sm + 2 * 64 * FPAD; // [64][FPAD]  Vs[k][d]

    const int t  = threadIdx.x;
    const int ty = t >> 4;           // 0..15 -> q rows ty*4..+3
    const int tx = t & 15;           // 0..15 -> cols tx*4..+3
    const int b  = blockIdx.z;
    const int h  = blockIdx.y;
    const int q0 = blockIdx.x * 64;
    const size_t base = (size_t)b * SEQ * DM + (size_t)h * DH;
    const float scale = 0.125f;      // DH^-0.5 = 64^-0.5

    // Load Q tile transposed + pre-scaled
#pragma unroll
    for (int i = 0; i < 4; i++) {
        int f   = t + i * 256;       // 0..1023
        int row = f >> 4;            // 0..63
        int dq  = (f & 15) << 2;     // 0,4,...,60
        float4 a = *(const float4*)(Q + base + (size_t)(q0 + row) * DM + dq);
        Qts[(dq + 0) * FPAD + row] = a.x * scale;
        Qts[(dq + 1) * FPAD + row] = a.y * scale;
        Qts[(dq + 2) * FPAD + row] = a.z * scale;
        Qts[(dq + 3) * FPAD + row] = a.w * scale;
    }

    float m_i[4], l_i[4], o[4][4];
#pragma unroll
    for (int r = 0; r < 4; r++) {
        m_i[r] = -3.0e38f; l_i[r] = 0.f;
#pragma unroll
        for (int c = 0; c < 4; c++) o[r][c] = 0.f;
    }

    for (int kt = 0; kt < SEQ / 64; kt++) {
        const int k0 = kt * 64;
        __syncthreads();   // prior PV reads done; also orders first Q load
#pragma unroll
        for (int i = 0; i < 4; i++) {
            int f   = t + i * 256;
            int row = f >> 4;
            int dq  = (f & 15) << 2;
            float4 kv = *(const float4*)(K + base + (size_t)(k0 + row) * DM + dq);
            Kts[(dq + 0) * FPAD + row] = kv.x;
            Kts[(dq + 1) * FPAD + row] = kv.y;
            Kts[(dq + 2) * FPAD + row] = kv.z;
            Kts[(dq + 3) * FPAD + row] = kv.w;
            float4 vv = *(const float4*)(V + base + (size_t)(k0 + row) * DM + dq);
            *(float4*)(Vs + row * FPAD + dq) = vv;
        }
        __syncthreads();

        // S = (Q*scale) @ K^T  -- 4x4 per thread
        float s[4][4];
#pragma unroll
        for (int r = 0; r < 4; r++)
#pragma unroll
            for (int c = 0; c < 4; c++) s[r][c] = 0.f;

#pragma unroll 16
        for (int d = 0; d < 64; d++) {
            float4 ra = *(const float4*)(Qts + d * FPAD + ty * 4);
            float4 rb = *(const float4*)(Kts + d * FPAD + tx * 4);
            float av[4] = {ra.x, ra.y, ra.z, ra.w};
            float bv[4] = {rb.x, rb.y, rb.z, rb.w};
#pragma unroll
            for (int r = 0; r < 4; r++)
#pragma unroll
                for (int c = 0; c < 4; c++)
                    s[r][c] = fmaf(av[r], bv[c], s[r][c]);
        }

        // Online softmax (row stats shared across the 16 tx lanes of each ty)
        float alpha[4];
#pragma unroll
        for (int r = 0; r < 4; r++) {
            float mx = fmaxf(fmaxf(s[r][0], s[r][1]), fmaxf(s[r][2], s[r][3]));
            mx = grp_max16(mx);
            float mnew = fmaxf(m_i[r], mx);
            alpha[r] = __expf(m_i[r] - mnew);
            float rs = 0.f;
#pragma unroll
            for (int c = 0; c < 4; c++) {
                s[r][c] = __expf(s[r][c] - mnew);
                rs += s[r][c];
            }
            rs = grp_sum16(rs);
            l_i[r] = l_i[r] * alpha[r] + rs;
            m_i[r] = mnew;
#pragma unroll
            for (int c = 0; c < 4; c++) o[r][c] *= alpha[r];
        }

        __syncthreads();   // everyone done reading Kts
        // Write P transposed into Kts: Pts[k][r]
#pragma unroll
        for (int r = 0; r < 4; r++)
#pragma unroll
            for (int c = 0; c < 4; c++)
                Kts[(tx * 4 + c) * FPAD + ty * 4 + r] = s[r][c];
        __syncthreads();

        // O += P @ V
#pragma unroll 16
        for (int k = 0; k < 64; k++) {
            float4 pa = *(const float4*)(Kts + k * FPAD + ty * 4);
            float4 vb = *(const float4*)(Vs + k * FPAD + tx * 4);
            float pv[4] = {pa.x, pa.y, pa.z, pa.w};
            float vv[4] = {vb.x, vb.y, vb.z, vb.w};
#pragma unroll
            for (int r = 0; r < 4; r++)
#pragma unroll
                for (int c = 0; c < 4; c++)
                    o[r][c] = fmaf(pv[r], vv[c], o[r][c]);
        }
    }

    // Epilogue: normalize and store
#pragma unroll
    for (int r = 0; r < 4; r++) {
        float inv = 1.f / l_i[r];
        float4 w = {o[r][0] * inv, o[r][1] * inv, o[r][2] * inv, o[r][3] * inv};
        *(float4*)(O + base + (size_t)(q0 + ty * 4 + r) * DM + tx * 4) = w;
    }
}

// ---------------------------------------------------------------------------
// Launch
// ---------------------------------------------------------------------------
extern "C" void kernel_launch(void* const* d_in, const int* in_sizes, int n_in,
                              void* d_out, int out_size) {
    const float* x   = (const float*)d_in[0];
    const float* src = (const float*)d_in[1];
    const float* Wq  = (const float*)d_in[2];
    const float* Wk  = (const float*)d_in[3];
    const float* Wv  = (const float*)d_in[4];
    const float* Wo  = (const float*)d_in[5];
    float* out = (float*)d_out;

    float *Qb, *Kb, *Vb, *Ob;
    cudaGetSymbolAddress((void**)&Qb, g_Q);
    cudaGetSymbolAddress((void**)&Kb, g_K);
    cudaGetSymbolAddress((void**)&Vb, g_V);
    cudaGetSymbolAddress((void**)&Ob, g_O);

    cudaFuncSetAttribute(flash_attn, cudaFuncAttributeMaxDynamicSharedMemorySize,
                         FLASH_SMEM);

    dim3 ggrid(DM / 128, M_TOT / 128);   // (8, 32)
    gemm_xwt<<<ggrid, 256>>>(x,   Wq, Qb);
    gemm_xwt<<<ggrid, 256>>>(src, Wk, Kb);
    gemm_xwt<<<ggrid, 256>>>(src, Wv, Vb);

    dim3 agrid(SEQ / 64, NH, BATCH);     // (32, 16, 2)
    flash_attn<<<agrid, 256, FLASH_SMEM>>>(Qb, Kb, Vb, Ob);

    gemm_xwt<<<ggrid, 256>>>(Ob, Wo, out);
}

// round 4
// speedup vs baseline: 1.4135x; 1.4135x over previous
#include <cuda_runtime.h>
#include <cuda_bf16.h>
#include <cstdint>

#define DM     1024
#define NH     16
#define DH     64
#define SEQ    2048
#define BATCH  2
#define M_TOT  (BATCH * SEQ)   // 4096

// Scratch (no allocations allowed)
__device__ float g_Q[(size_t)M_TOT * DM];
__device__ float g_K[(size_t)M_TOT * DM];
__device__ float g_V[(size_t)M_TOT * DM];
__device__ float g_O[(size_t)M_TOT * DM];

// ===========================================================================
// Helpers
// ===========================================================================
__device__ __forceinline__ uint32_t smem_u32(const void* p) {
    uint32_t a;
    asm("{ .reg .u64 t; cvta.to.shared.u64 t, %1; cvt.u32.u64 %0, t; }"
        : "=r"(a) : "l"(p));
    return a;
}

__device__ __forceinline__ void ldsm4(uint32_t* r, uint32_t addr) {
    asm volatile("ldmatrix.sync.aligned.m8n8.x4.shared.b16 {%0,%1,%2,%3}, [%4];"
                 : "=r"(r[0]), "=r"(r[1]), "=r"(r[2]), "=r"(r[3]) : "r"(addr));
}
__device__ __forceinline__ void sts64(uint32_t addr, uint32_t a, uint32_t b) {
    asm volatile("st.shared.v2.b32 [%0], {%1, %2};" :: "r"(addr), "r"(a), "r"(b)
                 : "memory");
}

#define MMA_BF16(d, a, b0, b1) \
    asm volatile("mma.sync.aligned.m16n8k16.row.col.f32.bf16.bf16.f32 " \
                 "{%0,%1,%2,%3},{%4,%5,%6,%7},{%8,%9},{%0,%1,%2,%3};" \
                 : "+f"((d)[0]), "+f"((d)[1]), "+f"((d)[2]), "+f"((d)[3]) \
                 : "r"((a)[0]), "r"((a)[1]), "r"((a)[2]), "r"((a)[3]), \
                   "r"(b0), "r"(b1))

// Truncation hi-split: exact in fp32, hi = top-16-bits of the float.
__device__ __forceinline__ float trunc_hi(float x) {
    return __uint_as_float(__float_as_uint(x) & 0xFFFF0000u);
}
// Pack two floats' top-16-bits as bf16x2 {x->low, y->high}
__device__ __forceinline__ uint32_t pack_hi2(float x, float y) {
    return (__float_as_uint(y) & 0xFFFF0000u) | (__float_as_uint(x) >> 16);
}
// Pack two residuals as RN bf16x2 {x->low, y->high}
__device__ __forceinline__ uint32_t pack_rn2(float x, float y) {
    __nv_bfloat162 p = __floats2bfloat162_rn(x, y);
    return *reinterpret_cast<uint32_t*>(&p);
}

// ===========================================================================
// Split-bf16 GEMM via mma.sync: Y[m,n] = sum_k X[m,k]*W[n,k]  (Y = X@W^T)
// M=4096, N=K=1024. 128x128 CTA tile, KC=32, double-buffered smem,
// D = Ahi*Bhi + Ahi*Blo + Alo*Bhi  (error ~2^-16 per product).
// Smem rows padded to 40 bf16 (80B) -> conflict-free ldmatrix.
// ===========================================================================
#define KC   32
#define LDT  40                   // bf16 per smem row (padded)
#define TILE_BYTES (128 * LDT * 2)      // 10240
#define STAGE_BYTES (4 * TILE_BYTES)    // Ahi, Alo, Bhi, Blo
#define GSMEM (2 * STAGE_BYTES)         // 81920

__global__ __launch_bounds__(256, 1)
void gemm_bf16s(const float* __restrict__ X, const float* __restrict__ W,
                float* __restrict__ Y) {
    extern __shared__ __align__(16) char sm[];
    const uint32_t sbase = smem_u32(sm);

    const int t    = threadIdx.x;
    const int lane = t & 31;
    const int wid  = t >> 5;
    const int wm   = wid & 1;          // 2 warps in M
    const int wn   = wid >> 1;         // 4 warps in N
    const int m0   = blockIdx.y * 128;
    const int n0   = blockIdx.x * 128;

    float acc[4][4][4];
#pragma unroll
    for (int mi = 0; mi < 4; mi++)
#pragma unroll
        for (int ni = 0; ni < 4; ni++)
#pragma unroll
            for (int e = 0; e < 4; e++) acc[mi][ni][e] = 0.f;

    // Per-thread global load slots: idx = i*256+t; row = idx>>3; q = (idx&7)*4
    float4 ra[4], rb[4];

    auto ldg = [&](int k0) {
#pragma unroll
        for (int i = 0; i < 4; i++) {
            int idx = i * 256 + t;
            int row = idx >> 3;
            int q   = (idx & 7) << 2;
            ra[i] = *(const float4*)(X + (size_t)(m0 + row) * DM + k0 + q);
            rb[i] = *(const float4*)(W + (size_t)(n0 + row) * DM + k0 + q);
        }
    };

    auto cvt_sts = [&](uint32_t sb) {
        const uint32_t a_hi = sb;
        const uint32_t a_lo = sb + TILE_BYTES;
        const uint32_t b_hi = sb + 2 * TILE_BYTES;
        const uint32_t b_lo = sb + 3 * TILE_BYTES;
#pragma unroll
        for (int i = 0; i < 4; i++) {
            int idx = i * 256 + t;
            int row = idx >> 3;
            int q   = (idx & 7) << 2;
            uint32_t off = (uint32_t)row * (LDT * 2) + (uint32_t)q * 2;

            float4 a = ra[i];
            sts64(a_hi + off, pack_hi2(a.x, a.y), pack_hi2(a.z, a.w));
            sts64(a_lo + off,
                  pack_rn2(a.x - trunc_hi(a.x), a.y - trunc_hi(a.y)),
                  pack_rn2(a.z - trunc_hi(a.z), a.w - trunc_hi(a.w)));

            float4 b = rb[i];
            sts64(b_hi + off, pack_hi2(b.x, b.y), pack_hi2(b.z, b.w));
            sts64(b_lo + off,
                  pack_rn2(b.x - trunc_hi(b.x), b.y - trunc_hi(b.y)),
                  pack_rn2(b.z - trunc_hi(b.z), b.w - trunc_hi(b.w)));
        }
    };

    // ldmatrix address components (within a 128xLDT tile)
    const int r8  = lane & 7;
    const int sel = lane >> 3;
    // A: mat0 (m0-7,k0) mat1 (m8-15,k0) mat2 (m0-7,k8) mat3 (m8-15,k8)
    const uint32_t aRowOff = (uint32_t)(wm * 64 + (sel & 1) * 8 + r8) * (LDT * 2);
    const uint32_t aKOff   = (uint32_t)((sel >> 1) * 8) * 2;
    // B (plain ldmatrix on [n][k]): mat0 (n0-7,k0) mat1 (n0-7,k8)
    //                               mat2 (n8-15,k0) mat3 (n8-15,k8)
    const uint32_t bRowBase = (uint32_t)(wn * 32 + (sel >> 1) * 8 + r8) * (LDT * 2);
    const uint32_t bKOff    = (uint32_t)((sel & 1) * 8) * 2;

    auto compute = [&](uint32_t sb) {
#pragma unroll
        for (int ks = 0; ks < 2; ks++) {
            const uint32_t kb = (uint32_t)ks * 16 * 2;
#pragma unroll
            for (int c = 0; c < 3; c++) {
                const uint32_t abase = sb + (c == 2 ? TILE_BYTES : 0u);
                const uint32_t bbase = sb + 2 * TILE_BYTES + (c == 1 ? TILE_BYTES : 0u);
                uint32_t afr[4][4];
#pragma unroll
                for (int mi = 0; mi < 4; mi++)
                    ldsm4(afr[mi], abase + aRowOff
                                 + (uint32_t)(mi * 16) * (LDT * 2) + kb + aKOff);
                uint32_t bfr[2][4];
#pragma unroll
                for (int np = 0; np < 2; np++)
                    ldsm4(bfr[np], bbase + bRowBase
                                 + (uint32_t)(np * 16) * (LDT * 2) + kb + bKOff);
#pragma unroll
                for (int mi = 0; mi < 4; mi++)
#pragma unroll
                    for (int ni = 0; ni < 4; ni++)
                        MMA_BF16(acc[mi][ni], afr[mi],
                                 bfr[ni >> 1][(ni & 1) * 2],
                                 bfr[ni >> 1][(ni & 1) * 2 + 1]);
            }
        }
    };

    // Prologue
    ldg(0);
    cvt_sts(sbase);
    __syncthreads();

    const int NCHUNK = DM / KC;    // 32
    for (int chunk = 0; chunk < NCHUNK; chunk++) {
        const int s = chunk & 1;
        const bool more = (chunk + 1 < NCHUNK);
        if (more) ldg((chunk + 1) * KC);
        compute(sbase + (uint32_t)s * STAGE_BYTES);
        if (more) {
            __syncthreads();
            cvt_sts(sbase + (uint32_t)(s ^ 1) * STAGE_BYTES);
            __syncthreads();
        }
    }

    // Epilogue: standard m16n8 fragment layout
    const int g  = lane >> 2;
    const int c2 = (lane & 3) * 2;
#pragma unroll
    for (int mi = 0; mi < 4; mi++) {
#pragma unroll
        for (int ni = 0; ni < 4; ni++) {
            int row = m0 + wm * 64 + mi * 16 + g;
            int col = n0 + wn * 32 + ni * 8 + c2;
            float2 v0 = {acc[mi][ni][0], acc[mi][ni][1]};
            float2 v1 = {acc[mi][ni][2], acc[mi][ni][3]};
            *(float2*)(Y + (size_t)row * DM + col)       = v0;
            *(float2*)(Y + (size_t)(row + 8) * DM + col) = v1;
        }
    }
}

// ---------------------------------------------------------------------------
// Flash attention (unchanged from R1): per (b,h), 64 q-rows per block.
// ---------------------------------------------------------------------------
#define FPAD 68
#define FLASH_SMEM (3 * 64 * FPAD * 4)

__device__ __forceinline__ float grp_max16(float v) {
    v = fmaxf(v, __shfl_xor_sync(0xffffffffu, v, 1));
    v = fmaxf(v, __shfl_xor_sync(0xffffffffu, v, 2));
    v = fmaxf(v, __shfl_xor_sync(0xffffffffu, v, 4));
    v = fmaxf(v, __shfl_xor_sync(0xffffffffu, v, 8));
    return v;
}
__device__ __forceinline__ float grp_sum16(float v) {
    v += __shfl_xor_sync(0xffffffffu, v, 1);
    v += __shfl_xor_sync(0xffffffffu, v, 2);
    v += __shfl_xor_sync(0xffffffffu, v, 4);
    v += __shfl_xor_sync(0xffffffffu, v, 8);
    return v;
}

__global__ __launch_bounds__(256) void flash_attn(const float* __restrict__ Q,
                                                  const float* __restrict__ K,
                                                  const float* __restrict__ V,
                                                  float* __restrict__ O) {
    extern __shared__ __align__(16) float smf[];
    float* Qts = smf;
    float* Kts = smf + 64 * FPAD;
    float* Vs  = smf + 2 * 64 * FPAD;

    const int t  = threadIdx.x;
    const int ty = t >> 4;
    const int tx = t & 15;
    const int b  = blockIdx.z;
    const int h  = blockIdx.y;
    const int q0 = blockIdx.x * 64;
    const size_t base = (size_t)b * SEQ * DM + (size_t)h * DH;
    const float scale = 0.125f;

#pragma unroll
    for (int i = 0; i < 4; i++) {
        int f   = t + i * 256;
        int row = f >> 4;
        int dq  = (f & 15) << 2;
        float4 a = *(const float4*)(Q + base + (size_t)(q0 + row) * DM + dq);
        Qts[(dq + 0) * FPAD + row] = a.x * scale;
        Qts[(dq + 1) * FPAD + row] = a.y * scale;
        Qts[(dq + 2) * FPAD + row] = a.z * scale;
        Qts[(dq + 3) * FPAD + row] = a.w * scale;
    }

    float m_i[4], l_i[4], o[4][4];
#pragma unroll
    for (int r = 0; r < 4; r++) {
        m_i[r] = -3.0e38f; l_i[r] = 0.f;
#pragma unroll
        for (int c = 0; c < 4; c++) o[r][c] = 0.f;
    }

    for (int kt = 0; kt < SEQ / 64; kt++) {
        const int k0 = kt * 64;
        __syncthreads();
#pragma unroll
        for (int i = 0; i < 4; i++) {
            int f   = t + i * 256;
            int row = f >> 4;
            int dq  = (f & 15) << 2;
            float4 kv = *(const float4*)(K + base + (size_t)(k0 + row) * DM + dq);
            Kts[(dq + 0) * FPAD + row] = kv.x;
            Kts[(dq + 1) * FPAD + row] = kv.y;
            Kts[(dq + 2) * FPAD + row] = kv.z;
            Kts[(dq + 3) * FPAD + row] = kv.w;
            float4 vv = *(const float4*)(V + base + (size_t)(k0 + row) * DM + dq);
            *(float4*)(Vs + row * FPAD + dq) = vv;
        }
        __syncthreads();

        float s[4][4];
#pragma unroll
        for (int r = 0; r < 4; r++)
#pragma unroll
            for (int c = 0; c < 4; c++) s[r][c] = 0.f;

#pragma unroll 16
        for (int d = 0; d < 64; d++) {
            float4 ra = *(const float4*)(Qts + d * FPAD + ty * 4);
            float4 rb = *(const float4*)(Kts + d * FPAD + tx * 4);
            float av[4] = {ra.x, ra.y, ra.z, ra.w};
            float bv[4] = {rb.x, rb.y, rb.z, rb.w};
#pragma unroll
            for (int r = 0; r < 4; r++)
#pragma unroll
                for (int c = 0; c < 4; c++)
                    s[r][c] = fmaf(av[r], bv[c], s[r][c]);
        }

        float alpha[4];
#pragma unroll
        for (int r = 0; r < 4; r++) {
            float mx = fmaxf(fmaxf(s[r][0], s[r][1]), fmaxf(s[r][2], s[r][3]));
            mx = grp_max16(mx);
            float mnew = fmaxf(m_i[r], mx);
            alpha[r] = __expf(m_i[r] - mnew);
            float rs = 0.f;
#pragma unroll
            for (int c = 0; c < 4; c++) {
                s[r][c] = __expf(s[r][c] - mnew);
                rs += s[r][c];
            }
            rs = grp_sum16(rs);
            l_i[r] = l_i[r] * alpha[r] + rs;
            m_i[r] = mnew;
#pragma unroll
            for (int c = 0; c < 4; c++) o[r][c] *= alpha[r];
        }

        __syncthreads();
#pragma unroll
        for (int r = 0; r < 4; r++)
#pragma unroll
            for (int c = 0; c < 4; c++)
                Kts[(tx * 4 + c) * FPAD + ty * 4 + r] = s[r][c];
        __syncthreads();

#pragma unroll 16
        for (int k = 0; k < 64; k++) {
            float4 pa = *(const float4*)(Kts + k * FPAD + ty * 4);
            float4 vb = *(const float4*)(Vs + k * FPAD + tx * 4);
            float pv[4] = {pa.x, pa.y, pa.z, pa.w};
            float vv[4] = {vb.x, vb.y, vb.z, vb.w};
#pragma unroll
            for (int r = 0; r < 4; r++)
#pragma unroll
                for (int c = 0; c < 4; c++)
                    o[r][c] = fmaf(pv[r], vv[c], o[r][c]);
        }
    }

#pragma unroll
    for (int r = 0; r < 4; r++) {
        float inv = 1.f / l_i[r];
        float4 w = {o[r][0] * inv, o[r][1] * inv, o[r][2] * inv, o[r][3] * inv};
        *(float4*)(O + base + (size_t)(q0 + ty * 4 + r) * DM + tx * 4) = w;
    }
}

// ---------------------------------------------------------------------------
// Launch
// ---------------------------------------------------------------------------
extern "C" void kernel_launch(void* const* d_in, const int* in_sizes, int n_in,
                              void* d_out, int out_size) {
    const float* x   = (const float*)d_in[0];
    const float* src = (const float*)d_in[1];
    const float* Wq  = (const float*)d_in[2];
    const float* Wk  = (const float*)d_in[3];
    const float* Wv  = (const float*)d_in[4];
    const float* Wo  = (const float*)d_in[5];
    float* out = (float*)d_out;

    float *Qb, *Kb, *Vb, *Ob;
    cudaGetSymbolAddress((void**)&Qb, g_Q);
    cudaGetSymbolAddress((void**)&Kb, g_K);
    cudaGetSymbolAddress((void**)&Vb, g_V);
    cudaGetSymbolAddress((void**)&Ob, g_O);

    cudaFuncSetAttribute(gemm_bf16s, cudaFuncAttributeMaxDynamicSharedMemorySize,
                         GSMEM);
    cudaFuncSetAttribute(flash_attn, cudaFuncAttributeMaxDynamicSharedMemorySize,
                         FLASH_SMEM);

    dim3 ggrid(DM / 128, M_TOT / 128);   // (8, 32)
    gemm_bf16s<<<ggrid, 256, GSMEM>>>(x,   Wq, Qb);
    gemm_bf16s<<<ggrid, 256, GSMEM>>>(src, Wk, Kb);
    gemm_bf16s<<<ggrid, 256, GSMEM>>>(src, Wv, Vb);

    dim3 agrid(SEQ / 64, NH, BATCH);     // (32, 16, 2)
    flash_attn<<<agrid, 256, FLASH_SMEM>>>(Qb, Kb, Vb, Ob);

    gemm_bf16s<<<ggrid, 256, GSMEM>>>(Ob, Wo, out);
}

// round 6
// speedup vs baseline: 2.8945x; 2.0478x over previous
#include <cuda_runtime.h>
#include <cuda_bf16.h>
#include <cstdint>

#define DM     1024
#define NH     16
#define DH     64
#define SEQ    2048
#define BATCH  2
#define M_TOT  (BATCH * SEQ)   // 4096

// Scratch (no allocations allowed)
__device__ float g_Q[(size_t)M_TOT * DM];
__device__ float g_K[(size_t)M_TOT * DM];
__device__ float g_V[(size_t)M_TOT * DM];
__device__ float g_O[(size_t)M_TOT * DM];

// ===========================================================================
// Helpers
// ===========================================================================
__device__ __forceinline__ uint32_t smem_u32(const void* p) {
    uint32_t a;
    asm("{ .reg .u64 t; cvta.to.shared.u64 t, %1; cvt.u32.u64 %0, t; }"
        : "=r"(a) : "l"(p));
    return a;
}

__device__ __forceinline__ void ldsm4(uint32_t* r, uint32_t addr) {
    asm volatile("ldmatrix.sync.aligned.m8n8.x4.shared.b16 {%0,%1,%2,%3}, [%4];"
                 : "=r"(r[0]), "=r"(r[1]), "=r"(r[2]), "=r"(r[3]) : "r"(addr));
}
__device__ __forceinline__ void ldsm4t(uint32_t* r, uint32_t addr) {
    asm volatile("ldmatrix.sync.aligned.m8n8.x4.trans.shared.b16 {%0,%1,%2,%3}, [%4];"
                 : "=r"(r[0]), "=r"(r[1]), "=r"(r[2]), "=r"(r[3]) : "r"(addr));
}
__device__ __forceinline__ void sts64(uint32_t addr, uint32_t a, uint32_t b) {
    asm volatile("st.shared.v2.b32 [%0], {%1, %2};" :: "r"(addr), "r"(a), "r"(b)
                 : "memory");
}

#define MMA_BF16(d, a, b0, b1) \
    asm volatile("mma.sync.aligned.m16n8k16.row.col.f32.bf16.bf16.f32 " \
                 "{%0,%1,%2,%3},{%4,%5,%6,%7},{%8,%9},{%0,%1,%2,%3};" \
                 : "+f"((d)[0]), "+f"((d)[1]), "+f"((d)[2]), "+f"((d)[3]) \
                 : "r"((a)[0]), "r"((a)[1]), "r"((a)[2]), "r"((a)[3]), \
                   "r"(b0), "r"(b1))

__device__ __forceinline__ float trunc_hi(float x) {
    return __uint_as_float(__float_as_uint(x) & 0xFFFF0000u);
}
__device__ __forceinline__ uint32_t pack_hi2(float x, float y) {
    return (__float_as_uint(y) & 0xFFFF0000u) | (__float_as_uint(x) >> 16);
}
__device__ __forceinline__ uint32_t pack_rn2(float x, float y) {
    __nv_bfloat162 p = __floats2bfloat162_rn(x, y);
    return *reinterpret_cast<uint32_t*>(&p);
}

// Fast exp2 on FMA pipe (no MUFU). Valid for x <= ~0 (clamped at -126).
__device__ __forceinline__ float fexp2(float x) {
    x = fmaxf(x, -126.0f);
    float z = x + 12582912.0f;           // 1.5*2^23: RN -> round(x)
    float f = x - (z - 12582912.0f);     // f in [-0.5, 0.5]
    float p = 0.0013333558f;
    p = fmaf(p, f, 0.0096181291f);
    p = fmaf(p, f, 0.0555041087f);
    p = fmaf(p, f, 0.2402265069f);
    p = fmaf(p, f, 0.6931471806f);
    p = fmaf(p, f, 1.0f);
    return __uint_as_float(__float_as_uint(p) + (__float_as_uint(z) << 23));
}

// ===========================================================================
// Split-bf16 GEMM via mma.sync (unchanged — validated R4)
// ===========================================================================
#define KC   32
#define LDT  40
#define TILE_BYTES (128 * LDT * 2)
#define STAGE_BYTES (4 * TILE_BYTES)
#define GSMEM (2 * STAGE_BYTES)

__global__ __launch_bounds__(256, 1)
void gemm_bf16s(const float* __restrict__ X, const float* __restrict__ W,
                float* __restrict__ Y) {
    extern __shared__ __align__(16) char sm[];
    const uint32_t sbase = smem_u32(sm);

    const int t    = threadIdx.x;
    const int lane = t & 31;
    const int wid  = t >> 5;
    const int wm   = wid & 1;
    const int wn   = wid >> 1;
    const int m0   = blockIdx.y * 128;
    const int n0   = blockIdx.x * 128;

    float acc[4][4][4];
#pragma unroll
    for (int mi = 0; mi < 4; mi++)
#pragma unroll
        for (int ni = 0; ni < 4; ni++)
#pragma unroll
            for (int e = 0; e < 4; e++) acc[mi][ni][e] = 0.f;

    float4 ra[4], rb[4];

    auto ldg = [&](int k0) {
#pragma unroll
        for (int i = 0; i < 4; i++) {
            int idx = i * 256 + t;
            int row = idx >> 3;
            int q   = (idx & 7) << 2;
            ra[i] = *(const float4*)(X + (size_t)(m0 + row) * DM + k0 + q);
            rb[i] = *(const float4*)(W + (size_t)(n0 + row) * DM + k0 + q);
        }
    };

    auto cvt_sts = [&](uint32_t sb) {
        const uint32_t a_hi = sb;
        const uint32_t a_lo = sb + TILE_BYTES;
        const uint32_t b_hi = sb + 2 * TILE_BYTES;
        const uint32_t b_lo = sb + 3 * TILE_BYTES;
#pragma unroll
        for (int i = 0; i < 4; i++) {
            int idx = i * 256 + t;
            int row = idx >> 3;
            int q   = (idx & 7) << 2;
            uint32_t off = (uint32_t)row * (LDT * 2) + (uint32_t)q * 2;

            float4 a = ra[i];
            sts64(a_hi + off, pack_hi2(a.x, a.y), pack_hi2(a.z, a.w));
            sts64(a_lo + off,
                  pack_rn2(a.x - trunc_hi(a.x), a.y - trunc_hi(a.y)),
                  pack_rn2(a.z - trunc_hi(a.z), a.w - trunc_hi(a.w)));

            float4 b = rb[i];
            sts64(b_hi + off, pack_hi2(b.x, b.y), pack_hi2(b.z, b.w));
            sts64(b_lo + off,
                  pack_rn2(b.x - trunc_hi(b.x), b.y - trunc_hi(b.y)),
                  pack_rn2(b.z - trunc_hi(b.z), b.w - trunc_hi(b.w)));
        }
    };

    const int r8  = lane & 7;
    const int sel = lane >> 3;
    const uint32_t aRowOff = (uint32_t)(wm * 64 + (sel & 1) * 8 + r8) * (LDT * 2);
    const uint32_t aKOff   = (uint32_t)((sel >> 1) * 8) * 2;
    const uint32_t bRowBase = (uint32_t)(wn * 32 + (sel >> 1) * 8 + r8) * (LDT * 2);
    const uint32_t bKOff    = (uint32_t)((sel & 1) * 8) * 2;

    auto compute = [&](uint32_t sb) {
#pragma unroll
        for (int ks = 0; ks < 2; ks++) {
            const uint32_t kb = (uint32_t)ks * 16 * 2;
#pragma unroll
            for (int c = 0; c < 3; c++) {
                const uint32_t abase = sb + (c == 2 ? TILE_BYTES : 0u);
                const uint32_t bbase = sb + 2 * TILE_BYTES + (c == 1 ? TILE_BYTES : 0u);
                uint32_t afr[4][4];
#pragma unroll
                for (int mi = 0; mi < 4; mi++)
                    ldsm4(afr[mi], abase + aRowOff
                                 + (uint32_t)(mi * 16) * (LDT * 2) + kb + aKOff);
                uint32_t bfr[2][4];
#pragma unroll
                for (int np = 0; np < 2; np++)
                    ldsm4(bfr[np], bbase + bRowBase
                                 + (uint32_t)(np * 16) * (LDT * 2) + kb + bKOff);
#pragma unroll
                for (int mi = 0; mi < 4; mi++)
#pragma unroll
                    for (int ni = 0; ni < 4; ni++)
                        MMA_BF16(acc[mi][ni], afr[mi],
                                 bfr[ni >> 1][(ni & 1) * 2],
                                 bfr[ni >> 1][(ni & 1) * 2 + 1]);
            }
        }
    };

    ldg(0);
    cvt_sts(sbase);
    __syncthreads();

    const int NCHUNK = DM / KC;
    for (int chunk = 0; chunk < NCHUNK; chunk++) {
        const int s = chunk & 1;
        const bool more = (chunk + 1 < NCHUNK);
        if (more) ldg((chunk + 1) * KC);
        compute(sbase + (uint32_t)s * STAGE_BYTES);
        if (more) {
            __syncthreads();
            cvt_sts(sbase + (uint32_t)(s ^ 1) * STAGE_BYTES);
            __syncthreads();
        }
    }

    const int g  = lane >> 2;
    const int c2 = (lane & 3) * 2;
#pragma unroll
    for (int mi = 0; mi < 4; mi++) {
#pragma unroll
        for (int ni = 0; ni < 4; ni++) {
            int row = m0 + wm * 64 + mi * 16 + g;
            int col = n0 + wn * 32 + ni * 8 + c2;
            float2 v0 = {acc[mi][ni][0], acc[mi][ni][1]};
            float2 v1 = {acc[mi][ni][2], acc[mi][ni][3]};
            *(float2*)(Y + (size_t)row * DM + col)       = v0;
            *(float2*)(Y + (size_t)(row + 8) * DM + col) = v1;
        }
    }
}

// ===========================================================================
// Flash attention v3: tensor cores + FMA-pipe exp2 + FULL split precision.
// S  = Qhi.Khi + Qhi.Klo + Qlo.Khi (split-bf16)
// PV = Phi.Vhi + Phi.Vlo + Plo.Vhi (split-bf16)
// ===========================================================================
#define QSTR   72                        // bf16 per smem row (64 + pad 8)
#define QROW_B (QSTR * 2)                // 144 bytes
#define FQHI   0
#define FQLO   (128 * QROW_B)            // 18432
#define FKHI   (2 * 128 * QROW_B)        // 36864
#define FKLO   (FKHI + 64 * QROW_B)      // 46080
#define FVHI   (FKLO + 64 * QROW_B)      // 55296
#define FVLO   (FVHI + 64 * QROW_B)      // 64512
#define FSMEM  (FVLO + 64 * QROW_B)      // 73728

__global__ __launch_bounds__(256, 2)
void flash_v3(const float* __restrict__ Q, const float* __restrict__ K,
              const float* __restrict__ V, float* __restrict__ O) {
    extern __shared__ __align__(16) char fsm[];
    const uint32_t sb = smem_u32(fsm);

    const int t    = threadIdx.x;
    const int lane = t & 31;
    const int wid  = t >> 5;            // 0..7
    const int b    = blockIdx.z;
    const int h    = blockIdx.y;
    const int q0   = blockIdx.x * 128;
    const size_t base = (size_t)b * SEQ * DM + (size_t)h * DH;

    const float qs = 0.125f * 1.4426950408889634f;   // scale * log2(e)

    // ---- Stage Q (persistent), split hi/lo ----
#pragma unroll
    for (int i = 0; i < 8; i++) {
        int idx = i * 256 + t;
        int row = idx >> 4;
        int q   = (idx & 15) << 2;
        float4 a = *(const float4*)(Q + base + (size_t)(q0 + row) * DM + q);
        a.x *= qs; a.y *= qs; a.z *= qs; a.w *= qs;
        uint32_t off = (uint32_t)row * QROW_B + (uint32_t)q * 2;
        sts64(sb + FQHI + off, pack_hi2(a.x, a.y), pack_hi2(a.z, a.w));
        sts64(sb + FQLO + off,
              pack_rn2(a.x - trunc_hi(a.x), a.y - trunc_hi(a.y)),
              pack_rn2(a.z - trunc_hi(a.z), a.w - trunc_hi(a.w)));
    }

    const int r8  = lane & 7;
    const int sel = lane >> 3;
    const uint32_t aOff = (uint32_t)(wid * 16 + (sel & 1) * 8 + r8) * QROW_B
                        + (uint32_t)((sel >> 1) * 16);
    const uint32_t bOff = (uint32_t)((sel >> 1) * 8 + r8) * QROW_B
                        + (uint32_t)((sel & 1) * 16);
    const uint32_t vOff = (uint32_t)((sel & 1) * 8 + r8) * QROW_B
                        + (uint32_t)((sel >> 1) * 16);

    float m_s[2] = {-1.0e30f, -1.0e30f};
    float l_s[2] = {0.f, 0.f};
    float o[8][4];
#pragma unroll
    for (int j = 0; j < 8; j++)
#pragma unroll
        for (int e = 0; e < 4; e++) o[j][e] = 0.f;

    for (int kt = 0; kt < SEQ / 64; kt++) {
        const int k0 = kt * 64;
        __syncthreads();
        // ---- stage K and V, both split hi/lo ----
#pragma unroll
        for (int i = 0; i < 4; i++) {
            int idx = i * 256 + t;
            int row = idx >> 4;
            int q   = (idx & 15) << 2;
            uint32_t off = (uint32_t)row * QROW_B + (uint32_t)q * 2;
            float4 kv = *(const float4*)(K + base + (size_t)(k0 + row) * DM + q);
            sts64(sb + FKHI + off, pack_hi2(kv.x, kv.y), pack_hi2(kv.z, kv.w));
            sts64(sb + FKLO + off,
                  pack_rn2(kv.x - trunc_hi(kv.x), kv.y - trunc_hi(kv.y)),
                  pack_rn2(kv.z - trunc_hi(kv.z), kv.w - trunc_hi(kv.w)));
            float4 vv = *(const float4*)(V + base + (size_t)(k0 + row) * DM + q);
            sts64(sb + FVHI + off, pack_hi2(vv.x, vv.y), pack_hi2(vv.z, vv.w));
            sts64(sb + FVLO + off,
                  pack_rn2(vv.x - trunc_hi(vv.x), vv.y - trunc_hi(vv.y)),
                  pack_rn2(vv.z - trunc_hi(vv.z), vv.w - trunc_hi(vv.w)));
        }
        __syncthreads();

        // ---- S = Q' @ K^T (split) ----
        float s[8][4];
#pragma unroll
        for (int j = 0; j < 8; j++)
#pragma unroll
            for (int e = 0; e < 4; e++) s[j][e] = 0.f;

#pragma unroll
        for (int kc = 0; kc < 4; kc++) {
            const uint32_t kb = (uint32_t)kc * 32;
            uint32_t ahi[4], alo[4];
            ldsm4(ahi, sb + FQHI + aOff + kb);
            ldsm4(alo, sb + FQLO + aOff + kb);
#pragma unroll
            for (int j = 0; j < 4; j++) {
                const uint32_t rowj = (uint32_t)(j * 16) * QROW_B;
                uint32_t bh[4], bl[4];
                ldsm4(bh, sb + FKHI + bOff + rowj + kb);
                ldsm4(bl, sb + FKLO + bOff + rowj + kb);
                MMA_BF16(s[2 * j],     ahi, bh[0], bh[1]);
                MMA_BF16(s[2 * j + 1], ahi, bh[2], bh[3]);
                MMA_BF16(s[2 * j],     ahi, bl[0], bl[1]);
                MMA_BF16(s[2 * j + 1], ahi, bl[2], bl[3]);
                MMA_BF16(s[2 * j],     alo, bh[0], bh[1]);
                MMA_BF16(s[2 * j + 1], alo, bh[2], bh[3]);
            }
        }

        // ---- online softmax (log2 domain) ----
        float mx0 = s[0][0], mx1 = s[0][2];
#pragma unroll
        for (int j = 0; j < 8; j++) {
            mx0 = fmaxf(mx0, fmaxf(s[j][0], s[j][1]));
            mx1 = fmaxf(mx1, fmaxf(s[j][2], s[j][3]));
        }
        mx0 = fmaxf(mx0, __shfl_xor_sync(0xffffffffu, mx0, 1));
        mx0 = fmaxf(mx0, __shfl_xor_sync(0xffffffffu, mx0, 2));
        mx1 = fmaxf(mx1, __shfl_xor_sync(0xffffffffu, mx1, 1));
        mx1 = fmaxf(mx1, __shfl_xor_sync(0xffffffffu, mx1, 2));

        const float mn0 = fmaxf(m_s[0], mx0);
        const float mn1 = fmaxf(m_s[1], mx1);
        const float al0 = fexp2(m_s[0] - mn0);
        const float al1 = fexp2(m_s[1] - mn1);
        m_s[0] = mn0; m_s[1] = mn1;

        float sum0 = 0.f, sum1 = 0.f;
#pragma unroll
        for (int j = 0; j < 8; j++) {
            s[j][0] = fexp2(s[j][0] - mn0);
            s[j][1] = fexp2(s[j][1] - mn0);
            s[j][2] = fexp2(s[j][2] - mn1);
            s[j][3] = fexp2(s[j][3] - mn1);
            sum0 += s[j][0] + s[j][1];
            sum1 += s[j][2] + s[j][3];
        }
        sum0 += __shfl_xor_sync(0xffffffffu, sum0, 1);
        sum0 += __shfl_xor_sync(0xffffffffu, sum0, 2);
        sum1 += __shfl_xor_sync(0xffffffffu, sum1, 1);
        sum1 += __shfl_xor_sync(0xffffffffu, sum1, 2);
        l_s[0] = l_s[0] * al0 + sum0;
        l_s[1] = l_s[1] * al1 + sum1;

#pragma unroll
        for (int j = 0; j < 8; j++) {
            o[j][0] *= al0; o[j][1] *= al0;
            o[j][2] *= al1; o[j][3] *= al1;
        }

        // ---- P split into hi/lo fragments + PV (3-combo split) ----
#pragma unroll
        for (int kk = 0; kk < 4; kk++) {
            float* s0 = s[2 * kk];
            float* s1 = s[2 * kk + 1];
            uint32_t ph[4], pl[4];
            ph[0] = pack_hi2(s0[0], s0[1]);
            ph[1] = pack_hi2(s0[2], s0[3]);
            ph[2] = pack_hi2(s1[0], s1[1]);
            ph[3] = pack_hi2(s1[2], s1[3]);
            pl[0] = pack_rn2(s0[0] - trunc_hi(s0[0]), s0[1] - trunc_hi(s0[1]));
            pl[1] = pack_rn2(s0[2] - trunc_hi(s0[2]), s0[3] - trunc_hi(s0[3]));
            pl[2] = pack_rn2(s1[0] - trunc_hi(s1[0]), s1[1] - trunc_hi(s1[1]));
            pl[3] = pack_rn2(s1[2] - trunc_hi(s1[2]), s1[3] - trunc_hi(s1[3]));
            const uint32_t rowk = (uint32_t)(kk * 16) * QROW_B;
#pragma unroll
            for (int j = 0; j < 4; j++) {
                uint32_t vh[4], vl[4];
                ldsm4t(vh, sb + FVHI + vOff + rowk + (uint32_t)(j * 32));
                ldsm4t(vl, sb + FVLO + vOff + rowk + (uint32_t)(j * 32));
                MMA_BF16(o[2 * j],     ph, vh[0], vh[1]);
                MMA_BF16(o[2 * j + 1], ph, vh[2], vh[3]);
                MMA_BF16(o[2 * j],     ph, vl[0], vl[1]);
                MMA_BF16(o[2 * j + 1], ph, vl[2], vl[3]);
                MMA_BF16(o[2 * j],     pl, vh[0], vh[1]);
                MMA_BF16(o[2 * j + 1], pl, vh[2], vh[3]);
            }
        }
    }

    // ---- epilogue ----
    const int g  = lane >> 2;
    const int c2 = (lane & 3) * 2;
    const float inv0 = 1.f / l_s[0];
    const float inv1 = 1.f / l_s[1];
    const int row0 = q0 + wid * 16 + g;
#pragma unroll
    for (int j = 0; j < 8; j++) {
        float2 v0 = {o[j][0] * inv0, o[j][1] * inv0};
        float2 v1 = {o[j][2] * inv1, o[j][3] * inv1};
        *(float2*)(O + base + (size_t)row0 * DM + j * 8 + c2)       = v0;
        *(float2*)(O + base + (size_t)(row0 + 8) * DM + j * 8 + c2) = v1;
    }
}

// ---------------------------------------------------------------------------
// Launch
// ---------------------------------------------------------------------------
extern "C" void kernel_launch(void* const* d_in, const int* in_sizes, int n_in,
                              void* d_out, int out_size) {
    const float* x   = (const float*)d_in[0];
    const float* src = (const float*)d_in[1];
    const float* Wq  = (const float*)d_in[2];
    const float* Wk  = (const float*)d_in[3];
    const float* Wv  = (const float*)d_in[4];
    const float* Wo  = (const float*)d_in[5];
    float* out = (float*)d_out;

    float *Qb, *Kb, *Vb, *Ob;
    cudaGetSymbolAddress((void**)&Qb, g_Q);
    cudaGetSymbolAddress((void**)&Kb, g_K);
    cudaGetSymbolAddress((void**)&Vb, g_V);
    cudaGetSymbolAddress((void**)&Ob, g_O);

    cudaFuncSetAttribute(gemm_bf16s, cudaFuncAttributeMaxDynamicSharedMemorySize,
                         GSMEM);
    cudaFuncSetAttribute(flash_v3, cudaFuncAttributeMaxDynamicSharedMemorySize,
                         FSMEM);

    dim3 ggrid(DM / 128, M_TOT / 128);   // (8, 32)
    gemm_bf16s<<<ggrid, 256, GSMEM>>>(x,   Wq, Qb);
    gemm_bf16s<<<ggrid, 256, GSMEM>>>(src, Wk, Kb);
    gemm_bf16s<<<ggrid, 256, GSMEM>>>(src, Wv, Vb);

    dim3 agrid(SEQ / 128, NH, BATCH);    // (16, 16, 2)
    flash_v3<<<agrid, 256, FSMEM>>>(Qb, Kb, Vb, Ob);

    gemm_bf16s<<<ggrid, 256, GSMEM>>>(Ob, Wo, out);
}

// round 7
// speedup vs baseline: 2.9759x; 1.0281x over previous
#include <cuda_runtime.h>
#include <cuda_bf16.h>
#include <cstdint>

#define DM     1024
#define NH     16
#define DH     64
#define SEQ    2048
#define BATCH  2
#define M_TOT  (BATCH * SEQ)   // 4096

// Scratch (no allocations allowed)
__device__ float g_Q[(size_t)M_TOT * DM];
__device__ float g_K[(size_t)M_TOT * DM];
__device__ float g_V[(size_t)M_TOT * DM];
__device__ float g_O[(size_t)M_TOT * DM];

// ===========================================================================
// Helpers
// ===========================================================================
__device__ __forceinline__ uint32_t smem_u32(const void* p) {
    uint32_t a;
    asm("{ .reg .u64 t; cvta.to.shared.u64 t, %1; cvt.u32.u64 %0, t; }"
        : "=r"(a) : "l"(p));
    return a;
}

__device__ __forceinline__ void ldsm4(uint32_t* r, uint32_t addr) {
    asm volatile("ldmatrix.sync.aligned.m8n8.x4.shared.b16 {%0,%1,%2,%3}, [%4];"
                 : "=r"(r[0]), "=r"(r[1]), "=r"(r[2]), "=r"(r[3]) : "r"(addr));
}
__device__ __forceinline__ void ldsm4t(uint32_t* r, uint32_t addr) {
    asm volatile("ldmatrix.sync.aligned.m8n8.x4.trans.shared.b16 {%0,%1,%2,%3}, [%4];"
                 : "=r"(r[0]), "=r"(r[1]), "=r"(r[2]), "=r"(r[3]) : "r"(addr));
}
__device__ __forceinline__ void sts64(uint32_t addr, uint32_t a, uint32_t b) {
    asm volatile("st.shared.v2.b32 [%0], {%1, %2};" :: "r"(addr), "r"(a), "r"(b)
                 : "memory");
}

#define MMA_BF16(d, a, b0, b1) \
    asm volatile("mma.sync.aligned.m16n8k16.row.col.f32.bf16.bf16.f32 " \
                 "{%0,%1,%2,%3},{%4,%5,%6,%7},{%8,%9},{%0,%1,%2,%3};" \
                 : "+f"((d)[0]), "+f"((d)[1]), "+f"((d)[2]), "+f"((d)[3]) \
                 : "r"((a)[0]), "r"((a)[1]), "r"((a)[2]), "r"((a)[3]), \
                   "r"(b0), "r"(b1))

__device__ __forceinline__ float trunc_hi(float x) {
    return __uint_as_float(__float_as_uint(x) & 0xFFFF0000u);
}
__device__ __forceinline__ uint32_t pack_hi2(float x, float y) {
    return (__float_as_uint(y) & 0xFFFF0000u) | (__float_as_uint(x) >> 16);
}
__device__ __forceinline__ uint32_t pack_rn2(float x, float y) {
    __nv_bfloat162 p = __floats2bfloat162_rn(x, y);
    return *reinterpret_cast<uint32_t*>(&p);
}

// Fast exp2 on FMA pipe (no MUFU).
__device__ __forceinline__ float fexp2(float x) {
    x = fmaxf(x, -126.0f);
    float z = x + 12582912.0f;
    float f = x - (z - 12582912.0f);
    float p = 0.0013333558f;
    p = fmaf(p, f, 0.0096181291f);
    p = fmaf(p, f, 0.0555041087f);
    p = fmaf(p, f, 0.2402265069f);
    p = fmaf(p, f, 0.6931471806f);
    p = fmaf(p, f, 1.0f);
    return __uint_as_float(__float_as_uint(p) + (__float_as_uint(z) << 23));
}

// ===========================================================================
// Split-bf16 GEMM body (validated R4). Y = X @ W^T.
// ===========================================================================
#define KC   32
#define LDT  40
#define TILE_BYTES (128 * LDT * 2)
#define STAGE_BYTES (4 * TILE_BYTES)
#define GSMEM (2 * STAGE_BYTES)

__device__ __forceinline__ void gemm_body(const float* __restrict__ X,
                                          const float* __restrict__ W,
                                          float* __restrict__ Y,
                                          uint32_t sbase, int m0, int n0) {
    const int t    = threadIdx.x;
    const int lane = t & 31;
    const int wid  = t >> 5;
    const int wm   = wid & 1;
    const int wn   = wid >> 1;

    float acc[4][4][4];
#pragma unroll
    for (int mi = 0; mi < 4; mi++)
#pragma unroll
        for (int ni = 0; ni < 4; ni++)
#pragma unroll
            for (int e = 0; e < 4; e++) acc[mi][ni][e] = 0.f;

    float4 ra[4], rb[4];

    auto ldg = [&](int k0) {
#pragma unroll
        for (int i = 0; i < 4; i++) {
            int idx = i * 256 + t;
            int row = idx >> 3;
            int q   = (idx & 7) << 2;
            ra[i] = *(const float4*)(X + (size_t)(m0 + row) * DM + k0 + q);
            rb[i] = *(const float4*)(W + (size_t)(n0 + row) * DM + k0 + q);
        }
    };

    auto cvt_sts = [&](uint32_t sb) {
        const uint32_t a_hi = sb;
        const uint32_t a_lo = sb + TILE_BYTES;
        const uint32_t b_hi = sb + 2 * TILE_BYTES;
        const uint32_t b_lo = sb + 3 * TILE_BYTES;
#pragma unroll
        for (int i = 0; i < 4; i++) {
            int idx = i * 256 + t;
            int row = idx >> 3;
            int q   = (idx & 7) << 2;
            uint32_t off = (uint32_t)row * (LDT * 2) + (uint32_t)q * 2;

            float4 a = ra[i];
            sts64(a_hi + off, pack_hi2(a.x, a.y), pack_hi2(a.z, a.w));
            sts64(a_lo + off,
                  pack_rn2(a.x - trunc_hi(a.x), a.y - trunc_hi(a.y)),
                  pack_rn2(a.z - trunc_hi(a.z), a.w - trunc_hi(a.w)));

            float4 b = rb[i];
            sts64(b_hi + off, pack_hi2(b.x, b.y), pack_hi2(b.z, b.w));
            sts64(b_lo + off,
                  pack_rn2(b.x - trunc_hi(b.x), b.y - trunc_hi(b.y)),
                  pack_rn2(b.z - trunc_hi(b.z), b.w - trunc_hi(b.w)));
        }
    };

    const int r8  = lane & 7;
    const int sel = lane >> 3;
    const uint32_t aRowOff = (uint32_t)(wm * 64 + (sel & 1) * 8 + r8) * (LDT * 2);
    const uint32_t aKOff   = (uint32_t)((sel >> 1) * 8) * 2;
    const uint32_t bRowBase = (uint32_t)(wn * 32 + (sel >> 1) * 8 + r8) * (LDT * 2);
    const uint32_t bKOff    = (uint32_t)((sel & 1) * 8) * 2;

    auto compute = [&](uint32_t sb) {
#pragma unroll
        for (int ks = 0; ks < 2; ks++) {
            const uint32_t kb = (uint32_t)ks * 16 * 2;
#pragma unroll
            for (int c = 0; c < 3; c++) {
                const uint32_t abase = sb + (c == 2 ? TILE_BYTES : 0u);
                const uint32_t bbase = sb + 2 * TILE_BYTES + (c == 1 ? TILE_BYTES : 0u);
                uint32_t afr[4][4];
#pragma unroll
                for (int mi = 0; mi < 4; mi++)
                    ldsm4(afr[mi], abase + aRowOff
                                 + (uint32_t)(mi * 16) * (LDT * 2) + kb + aKOff);
                uint32_t bfr[2][4];
#pragma unroll
                for (int np = 0; np < 2; np++)
                    ldsm4(bfr[np], bbase + bRowBase
                                 + (uint32_t)(np * 16) * (LDT * 2) + kb + bKOff);
#pragma unroll
                for (int mi = 0; mi < 4; mi++)
#pragma unroll
                    for (int ni = 0; ni < 4; ni++)
                        MMA_BF16(acc[mi][ni], afr[mi],
                                 bfr[ni >> 1][(ni & 1) * 2],
                                 bfr[ni >> 1][(ni & 1) * 2 + 1]);
            }
        }
    };

    ldg(0);
    cvt_sts(sbase);
    __syncthreads();

    const int NCHUNK = DM / KC;
    for (int chunk = 0; chunk < NCHUNK; chunk++) {
        const int s = chunk & 1;
        const bool more = (chunk + 1 < NCHUNK);
        if (more) ldg((chunk + 1) * KC);
        compute(sbase + (uint32_t)s * STAGE_BYTES);
        if (more) {
            __syncthreads();
            cvt_sts(sbase + (uint32_t)(s ^ 1) * STAGE_BYTES);
            __syncthreads();
        }
    }

    const int g  = lane >> 2;
    const int c2 = (lane & 3) * 2;
#pragma unroll
    for (int mi = 0; mi < 4; mi++) {
#pragma unroll
        for (int ni = 0; ni < 4; ni++) {
            int row = m0 + wm * 64 + mi * 16 + g;
            int col = n0 + wn * 32 + ni * 8 + c2;
            float2 v0 = {acc[mi][ni][0], acc[mi][ni][1]};
            float2 v1 = {acc[mi][ni][2], acc[mi][ni][3]};
            *(float2*)(Y + (size_t)row * DM + col)       = v0;
            *(float2*)(Y + (size_t)(row + 8) * DM + col) = v1;
        }
    }
}

// Single GEMM (used for the output projection)
__global__ __launch_bounds__(256, 1)
void gemm_bf16s(const float* __restrict__ X, const float* __restrict__ W,
                float* __restrict__ Y) {
    extern __shared__ __align__(16) char sm[];
    gemm_body(X, W, Y, smem_u32(sm), blockIdx.y * 128, blockIdx.x * 128);
}

// Fused Q/K/V projections: blockIdx.z selects (X, W, Y).
__global__ __launch_bounds__(256, 1)
void gemm_qkv(const float* __restrict__ x, const float* __restrict__ src,
              const float* __restrict__ Wq, const float* __restrict__ Wk,
              const float* __restrict__ Wv,
              float* __restrict__ Qo, float* __restrict__ Ko,
              float* __restrict__ Vo) {
    extern __shared__ __align__(16) char sm[];
    const int z = blockIdx.z;
    const float* X = (z == 0) ? x : src;
    const float* W = (z == 0) ? Wq : (z == 1 ? Wk : Wv);
    float* Y       = (z == 0) ? Qo : (z == 1 ? Ko : Vo);
    gemm_body(X, W, Y, smem_u32(sm), blockIdx.y * 128, blockIdx.x * 128);
}

// ===========================================================================
// Flash attention v4: 128 threads / 64 q-rows per CTA, 4 CTAs/SM.
// Full split precision (validated R6 math), FMA-pipe exp2.
// ===========================================================================
#define QSTR   72                        // bf16 per smem row (64 + pad 8)
#define QROW_B (QSTR * 2)                // 144 bytes
#define FQHI   0
#define FQLO   (64 * QROW_B)             // 9216
#define FKHI   (2 * 64 * QROW_B)         // 18432
#define FKLO   (3 * 64 * QROW_B)         // 27648
#define FVHI   (4 * 64 * QROW_B)         // 36864
#define FVLO   (5 * 64 * QROW_B)         // 46080
#define FSMEM  (6 * 64 * QROW_B)         // 55296

__global__ __launch_bounds__(128, 4)
void flash_v4(const float* __restrict__ Q, const float* __restrict__ K,
              const float* __restrict__ V, float* __restrict__ O) {
    extern __shared__ __align__(16) char fsm[];
    const uint32_t sb = smem_u32(fsm);

    const int t    = threadIdx.x;
    const int lane = t & 31;
    const int wid  = t >> 5;            // 0..3
    const int b    = blockIdx.z;
    const int h    = blockIdx.y;
    const int q0   = blockIdx.x * 64;
    const size_t base = (size_t)b * SEQ * DM + (size_t)h * DH;

    const float qs = 0.125f * 1.4426950408889634f;   // scale * log2(e)

    // ---- Stage Q (persistent): 64 rows, split hi/lo ----
#pragma unroll
    for (int i = 0; i < 8; i++) {
        int idx = i * 128 + t;          // 0..1023
        int row = idx >> 4;             // 0..63
        int q   = (idx & 15) << 2;
        float4 a = *(const float4*)(Q + base + (size_t)(q0 + row) * DM + q);
        a.x *= qs; a.y *= qs; a.z *= qs; a.w *= qs;
        uint32_t off = (uint32_t)row * QROW_B + (uint32_t)q * 2;
        sts64(sb + FQHI + off, pack_hi2(a.x, a.y), pack_hi2(a.z, a.w));
        sts64(sb + FQLO + off,
              pack_rn2(a.x - trunc_hi(a.x), a.y - trunc_hi(a.y)),
              pack_rn2(a.z - trunc_hi(a.z), a.w - trunc_hi(a.w)));
    }

    const int r8  = lane & 7;
    const int sel = lane >> 3;
    const uint32_t aOff = (uint32_t)(wid * 16 + (sel & 1) * 8 + r8) * QROW_B
                        + (uint32_t)((sel >> 1) * 16);
    const uint32_t bOff = (uint32_t)((sel >> 1) * 8 + r8) * QROW_B
                        + (uint32_t)((sel & 1) * 16);
    const uint32_t vOff = (uint32_t)((sel & 1) * 8 + r8) * QROW_B
                        + (uint32_t)((sel >> 1) * 16);

    float m_s[2] = {-1.0e30f, -1.0e30f};
    float l_s[2] = {0.f, 0.f};
    float o[8][4];
#pragma unroll
    for (int j = 0; j < 8; j++)
#pragma unroll
        for (int e = 0; e < 4; e++) o[j][e] = 0.f;

    for (int kt = 0; kt < SEQ / 64; kt++) {
        const int k0 = kt * 64;
        __syncthreads();
        // ---- stage K and V, both split hi/lo ----
#pragma unroll
        for (int i = 0; i < 8; i++) {
            int idx = i * 128 + t;
            int row = idx >> 4;
            int q   = (idx & 15) << 2;
            uint32_t off = (uint32_t)row * QROW_B + (uint32_t)q * 2;
            float4 kv = *(const float4*)(K + base + (size_t)(k0 + row) * DM + q);
            sts64(sb + FKHI + off, pack_hi2(kv.x, kv.y), pack_hi2(kv.z, kv.w));
            sts64(sb + FKLO + off,
                  pack_rn2(kv.x - trunc_hi(kv.x), kv.y - trunc_hi(kv.y)),
                  pack_rn2(kv.z - trunc_hi(kv.z), kv.w - trunc_hi(kv.w)));
            float4 vv = *(const float4*)(V + base + (size_t)(k0 + row) * DM + q);
            sts64(sb + FVHI + off, pack_hi2(vv.x, vv.y), pack_hi2(vv.z, vv.w));
            sts64(sb + FVLO + off,
                  pack_rn2(vv.x - trunc_hi(vv.x), vv.y - trunc_hi(vv.y)),
                  pack_rn2(vv.z - trunc_hi(vv.z), vv.w - trunc_hi(vv.w)));
        }
        __syncthreads();

        // ---- S = Q' @ K^T (split) ----
        float s[8][4];
#pragma unroll
        for (int j = 0; j < 8; j++)
#pragma unroll
            for (int e = 0; e < 4; e++) s[j][e] = 0.f;

#pragma unroll
        for (int kc = 0; kc < 4; kc++) {
            const uint32_t kb = (uint32_t)kc * 32;
            uint32_t ahi[4], alo[4];
            ldsm4(ahi, sb + FQHI + aOff + kb);
            ldsm4(alo, sb + FQLO + aOff + kb);
#pragma unroll
            for (int j = 0; j < 4; j++) {
                const uint32_t rowj = (uint32_t)(j * 16) * QROW_B;
                uint32_t bh[4], bl[4];
                ldsm4(bh, sb + FKHI + bOff + rowj + kb);
                ldsm4(bl, sb + FKLO + bOff + rowj + kb);
                MMA_BF16(s[2 * j],     ahi, bh[0], bh[1]);
                MMA_BF16(s[2 * j + 1], ahi, bh[2], bh[3]);
                MMA_BF16(s[2 * j],     ahi, bl[0], bl[1]);
                MMA_BF16(s[2 * j + 1], ahi, bl[2], bl[3]);
                MMA_BF16(s[2 * j],     alo, bh[0], bh[1]);
                MMA_BF16(s[2 * j + 1], alo, bh[2], bh[3]);
            }
        }

        // ---- online softmax (log2 domain) ----
        float mx0 = s[0][0], mx1 = s[0][2];
#pragma unroll
        for (int j = 0; j < 8; j++) {
            mx0 = fmaxf(mx0, fmaxf(s[j][0], s[j][1]));
            mx1 = fmaxf(mx1, fmaxf(s[j][2], s[j][3]));
        }
        mx0 = fmaxf(mx0, __shfl_xor_sync(0xffffffffu, mx0, 1));
        mx0 = fmaxf(mx0, __shfl_xor_sync(0xffffffffu, mx0, 2));
        mx1 = fmaxf(mx1, __shfl_xor_sync(0xffffffffu, mx1, 1));
        mx1 = fmaxf(mx1, __shfl_xor_sync(0xffffffffu, mx1, 2));

        const float mn0 = fmaxf(m_s[0], mx0);
        const float mn1 = fmaxf(m_s[1], mx1);
        const float al0 = fexp2(m_s[0] - mn0);
        const float al1 = fexp2(m_s[1] - mn1);
        m_s[0] = mn0; m_s[1] = mn1;

        float sum0 = 0.f, sum1 = 0.f;
#pragma unroll
        for (int j = 0; j < 8; j++) {
            s[j][0] = fexp2(s[j][0] - mn0);
            s[j][1] = fexp2(s[j][1] - mn0);
            s[j][2] = fexp2(s[j][2] - mn1);
            s[j][3] = fexp2(s[j][3] - mn1);
            sum0 += s[j][0] + s[j][1];
            sum1 += s[j][2] + s[j][3];
        }
        sum0 += __shfl_xor_sync(0xffffffffu, sum0, 1);
        sum0 += __shfl_xor_sync(0xffffffffu, sum0, 2);
        sum1 += __shfl_xor_sync(0xffffffffu, sum1, 1);
        sum1 += __shfl_xor_sync(0xffffffffu, sum1, 2);
        l_s[0] = l_s[0] * al0 + sum0;
        l_s[1] = l_s[1] * al1 + sum1;

#pragma unroll
        for (int j = 0; j < 8; j++) {
            o[j][0] *= al0; o[j][1] *= al0;
            o[j][2] *= al1; o[j][3] *= al1;
        }

        // ---- P split hi/lo + PV (3-combo split) ----
#pragma unroll
        for (int kk = 0; kk < 4; kk++) {
            float* s0 = s[2 * kk];
            float* s1 = s[2 * kk + 1];
            uint32_t ph[4], pl[4];
            ph[0] = pack_hi2(s0[0], s0[1]);
            ph[1] = pack_hi2(s0[2], s0[3]);
            ph[2] = pack_hi2(s1[0], s1[1]);
            ph[3] = pack_hi2(s1[2], s1[3]);
            pl[0] = pack_rn2(s0[0] - trunc_hi(s0[0]), s0[1] - trunc_hi(s0[1]));
            pl[1] = pack_rn2(s0[2] - trunc_hi(s0[2]), s0[3] - trunc_hi(s0[3]));
            pl[2] = pack_rn2(s1[0] - trunc_hi(s1[0]), s1[1] - trunc_hi(s1[1]));
            pl[3] = pack_rn2(s1[2] - trunc_hi(s1[2]), s1[3] - trunc_hi(s1[3]));
            const uint32_t rowk = (uint32_t)(kk * 16) * QROW_B;
#pragma unroll
            for (int j = 0; j < 4; j++) {
                uint32_t vh[4], vl[4];
                ldsm4t(vh, sb + FVHI + vOff + rowk + (uint32_t)(j * 32));
                ldsm4t(vl, sb + FVLO + vOff + rowk + (uint32_t)(j * 32));
                MMA_BF16(o[2 * j],     ph, vh[0], vh[1]);
                MMA_BF16(o[2 * j + 1], ph, vh[2], vh[3]);
                MMA_BF16(o[2 * j],     ph, vl[0], vl[1]);
                MMA_BF16(o[2 * j + 1], ph, vl[2], vl[3]);
                MMA_BF16(o[2 * j],     pl, vh[0], vh[1]);
                MMA_BF16(o[2 * j + 1], pl, vh[2], vh[3]);
            }
        }
    }

    // ---- epilogue ----
    const int g  = lane >> 2;
    const int c2 = (lane & 3) * 2;
    const float inv0 = 1.f / l_s[0];
    const float inv1 = 1.f / l_s[1];
    const int row0 = q0 + wid * 16 + g;
#pragma unroll
    for (int j = 0; j < 8; j++) {
        float2 v0 = {o[j][0] * inv0, o[j][1] * inv0};
        float2 v1 = {o[j][2] * inv1, o[j][3] * inv1};
        *(float2*)(O + base + (size_t)row0 * DM + j * 8 + c2)       = v0;
        *(float2*)(O + base + (size_t)(row0 + 8) * DM + j * 8 + c2) = v1;
    }
}

// ---------------------------------------------------------------------------
// Launch
// ---------------------------------------------------------------------------
extern "C" void kernel_launch(void* const* d_in, const int* in_sizes, int n_in,
                              void* d_out, int out_size) {
    const float* x   = (const float*)d_in[0];
    const float* src = (const float*)d_in[1];
    const float* Wq  = (const float*)d_in[2];
    const float* Wk  = (const float*)d_in[3];
    const float* Wv  = (const float*)d_in[4];
    const float* Wo  = (const float*)d_in[5];
    float* out = (float*)d_out;

    float *Qb, *Kb, *Vb, *Ob;
    cudaGetSymbolAddress((void**)&Qb, g_Q);
    cudaGetSymbolAddress((void**)&Kb, g_K);
    cudaGetSymbolAddress((void**)&Vb, g_V);
    cudaGetSymbolAddress((void**)&Ob, g_O);

    cudaFuncSetAttribute(gemm_bf16s, cudaFuncAttributeMaxDynamicSharedMemorySize,
                         GSMEM);
    cudaFuncSetAttribute(gemm_qkv, cudaFuncAttributeMaxDynamicSharedMemorySize,
                         GSMEM);
    cudaFuncSetAttribute(flash_v4, cudaFuncAttributeMaxDynamicSharedMemorySize,
                         FSMEM);

    dim3 qkvgrid(DM / 128, M_TOT / 128, 3);   // (8, 32, 3)
    gemm_qkv<<<qkvgrid, 256, GSMEM>>>(x, src, Wq, Wk, Wv, Qb, Kb, Vb);

    dim3 agrid(SEQ / 64, NH, BATCH);          // (32, 16, 2)
    flash_v4<<<agrid, 128, FSMEM>>>(Qb, Kb, Vb, Ob);

    dim3 ggrid(DM / 128, M_TOT / 128);        // (8, 32)
    gemm_bf16s<<<ggrid, 256, GSMEM>>>(Ob, Wo, out);
}